// round 7
// baseline (speedup 1.0000x reference)
#include <cuda_runtime.h>
#include <math.h>

// Problem constants
constexpr int B   = 8;
constexpr int NT  = 1024;   // tokens
constexpr int C1  = 256;
constexpr int C2  = 512;
constexpr int C3  = 1024;
constexpr int KV  = 1792;
constexpr int H   = 4;
constexpr int HID = 2048;

// ---------------- single scratch pool with lifetime-based aliasing ----------------
// Region map (float offsets):
//   E   [0, 14680064)                       live steps 1..8
//   R1  [14680064, 44040192)  29,360,128 f  S1(3-4) -> T(6-7) -> ctx/res/x2(8..end)
//   R2  [44040192, 73400320)  29,360,128 f  q(2-3)+cx2(1-2) -> S/probs(4-6) -> Ts(7-8) -> h1(fc1-fc2)
constexpr long long OFF_E   = 0;
constexpr long long OFF_R1  = 14680064;
constexpr long long OFF_R2  = 44040192;
constexpr long long POOL_SZ = 73400320;               // 293.6 MB

constexpr long long OFF_S1  = OFF_R1;                 // [C2,KV] per (b,h)
constexpr long long OFF_T   = OFF_R1;
constexpr long long OFF_CTX = OFF_R1;                 // 4,194,304
constexpr long long OFF_RES = OFF_R1 + 4194304;       // 4,194,304
constexpr long long OFF_X2  = OFF_R1 + 8388608;       // 4,194,304
constexpr long long OFF_Q   = OFF_R2;                 // 16,777,216
constexpr long long OFF_CX2 = OFF_R2 + 17000448;      // 4,194,304 (disjoint from q)
constexpr long long OFF_S   = OFF_R2;                 // 29,360,128 (q,cx2 dead)
constexpr long long OFF_TS  = OFF_R2;                 // 7,340,032 (S dead)
constexpr long long OFF_H1  = OFF_R2;                 // 16,777,216 (Ts dead)

__device__ __align__(128) float g_pool[POOL_SZ];
__device__ __align__(128) float g_istd[B * H];

// =================================================================
// Generic 128x128x8 SGEMM, 256 threads, 8x8 per-thread microtile.
// OPA: 0 -> A is [M,K] row-major; 1 -> A is [K,M] row-major (A^T)
// OPB: 0 -> B is [K,N] row-major; 1 -> B is [N,K] row-major (B^T)
// EPI: 0 plain (alpha)  1 +R  2 +bias,gelu  3 +bias+R
// Requires M%128==0, N%128==0, K%8==0.
// =================================================================
template <int OPA, int OPB, int EPI>
__global__ void __launch_bounds__(256, 2) gemm_k(
    const float* __restrict__ A, const float* __restrict__ Bm,
    float* __restrict__ C,
    const float* __restrict__ bias, const float* __restrict__ R,
    int M, int Nn, int K,
    long long sAo, long long sAi, long long sBo, long long sBi,
    long long sC, int innerCnt, float alpha)
{
    __shared__ float As[8][132];
    __shared__ float Bs[8][132];

    const int z = blockIdx.z;
    A  += (long long)(z / innerCnt) * sAo + (long long)(z % innerCnt) * sAi;
    Bm += (long long)(z / innerCnt) * sBo + (long long)(z % innerCnt) * sBi;
    C  += (long long)z * sC;

    const int m0 = blockIdx.y * 128;
    const int n0 = blockIdx.x * 128;
    const int tid = threadIdx.x;
    const int tx = tid & 15, ty = tid >> 4;

    float acc[8][8];
#pragma unroll
    for (int i = 0; i < 8; i++)
#pragma unroll
        for (int j = 0; j < 8; j++) acc[i][j] = 0.f;

    for (int k0 = 0; k0 < K; k0 += 8) {
        if (OPA == 0) {
            const int m = tid >> 1, kq = (tid & 1) * 4;
            float4 v = *reinterpret_cast<const float4*>(&A[(long long)(m0 + m) * K + k0 + kq]);
            As[kq + 0][m] = v.x; As[kq + 1][m] = v.y;
            As[kq + 2][m] = v.z; As[kq + 3][m] = v.w;
        } else {
            const int k = tid >> 5, m4 = (tid & 31) * 4;
            *reinterpret_cast<float4*>(&As[k][m4]) =
                *reinterpret_cast<const float4*>(&A[(long long)(k0 + k) * M + m0 + m4]);
        }
        if (OPB == 0) {
            const int k = tid >> 5, n4 = (tid & 31) * 4;
            *reinterpret_cast<float4*>(&Bs[k][n4]) =
                *reinterpret_cast<const float4*>(&Bm[(long long)(k0 + k) * Nn + n0 + n4]);
        } else {
            const int n = tid >> 1, kq = (tid & 1) * 4;
            float4 v = *reinterpret_cast<const float4*>(&Bm[(long long)(n0 + n) * K + k0 + kq]);
            Bs[kq + 0][n] = v.x; Bs[kq + 1][n] = v.y;
            Bs[kq + 2][n] = v.z; Bs[kq + 3][n] = v.w;
        }
        __syncthreads();
#pragma unroll
        for (int kk = 0; kk < 8; kk++) {
            float a[8], b[8];
            *(float4*)&a[0] = *(float4*)&As[kk][ty * 8];
            *(float4*)&a[4] = *(float4*)&As[kk][ty * 8 + 4];
            *(float4*)&b[0] = *(float4*)&Bs[kk][tx * 8];
            *(float4*)&b[4] = *(float4*)&Bs[kk][tx * 8 + 4];
#pragma unroll
            for (int i = 0; i < 8; i++)
#pragma unroll
                for (int j = 0; j < 8; j++)
                    acc[i][j] = fmaf(a[i], b[j], acc[i][j]);
        }
        __syncthreads();
    }

#pragma unroll
    for (int i = 0; i < 8; i++) {
        const long long r = m0 + ty * 8 + i;
#pragma unroll
        for (int j = 0; j < 8; j += 4) {
            const long long cb = n0 + tx * 8 + j;
            float4 o;
            float* po = &o.x;
#pragma unroll
            for (int q = 0; q < 4; q++) {
                float v = acc[i][j + q] * alpha;
                const long long cc = cb + q;
                if (EPI == 1) v += R[r * Nn + cc];
                if (EPI == 2) { v += bias[cc]; v = 0.5f * v * (1.f + erff(v * 0.70710678118654752f)); }
                if (EPI == 3) { v += bias[cc] + R[r * Nn + cc]; }
                po[q] = v;
            }
            *reinterpret_cast<float4*>(&C[r * Nn + cb]) = o;
        }
    }
}

// ---------------- LayerNorm over concatenated [256|512|1024] row ----------------
__global__ void ln_concat_k(const float* __restrict__ e1, const float* __restrict__ e2,
                            const float* __restrict__ e3, const float* __restrict__ g,
                            const float* __restrict__ bta, float* __restrict__ out)
{
    const int r = blockIdx.x;           // [0, B*NT)
    const int t = threadIdx.x;          // 256
    float x[7], s = 0.f, sq = 0.f;
#pragma unroll
    for (int j = 0; j < 7; j++) {
        const int i = t + j * 256;
        float v;
        if (i < C1)            v = e1[(long long)r * C1 + i];
        else if (i < C1 + C2)  v = e2[(long long)r * C2 + (i - C1)];
        else                   v = e3[(long long)r * C3 + (i - C1 - C2)];
        x[j] = v; s += v; sq += v * v;
    }
    __shared__ float red[16];
#pragma unroll
    for (int o = 16; o; o >>= 1) { s += __shfl_xor_sync(~0u, s, o); sq += __shfl_xor_sync(~0u, sq, o); }
    const int w = t >> 5, l = t & 31;
    if (l == 0) { red[w] = s; red[8 + w] = sq; }
    __syncthreads();
    if (t < 32) {
        s  = (t < 8) ? red[t]     : 0.f;
        sq = (t < 8) ? red[8 + t] : 0.f;
#pragma unroll
        for (int o = 4; o; o >>= 1) { s += __shfl_xor_sync(~0u, s, o); sq += __shfl_xor_sync(~0u, sq, o); }
        if (t == 0) { red[0] = s; red[1] = sq; }
    }
    __syncthreads();
    const float mean = red[0] * (1.f / KV);
    const float var  = red[1] * (1.f / KV) - mean * mean;
    const float istd = rsqrtf(var + 1e-6f);
#pragma unroll
    for (int j = 0; j < 7; j++) {
        const int i = t + j * 256;
        out[(long long)r * KV + i] = (x[j] - mean) * istd * g[i] + bta[i];
    }
}

// ---------------- LayerNorm over 512-wide row ----------------
__global__ void ln512_k(const float* __restrict__ in, const float* __restrict__ g,
                        const float* __restrict__ bta, float* __restrict__ out)
{
    const int r = blockIdx.x;
    const int t = threadIdx.x;          // 256
    float x0 = in[(long long)r * C2 + t];
    float x1 = in[(long long)r * C2 + t + 256];
    float s = x0 + x1, sq = x0 * x0 + x1 * x1;
    __shared__ float red[16];
#pragma unroll
    for (int o = 16; o; o >>= 1) { s += __shfl_xor_sync(~0u, s, o); sq += __shfl_xor_sync(~0u, sq, o); }
    const int w = t >> 5, l = t & 31;
    if (l == 0) { red[w] = s; red[8 + w] = sq; }
    __syncthreads();
    if (t < 32) {
        s  = (t < 8) ? red[t]     : 0.f;
        sq = (t < 8) ? red[8 + t] : 0.f;
#pragma unroll
        for (int o = 4; o; o >>= 1) { s += __shfl_xor_sync(~0u, s, o); sq += __shfl_xor_sync(~0u, sq, o); }
        if (t == 0) { red[0] = s; red[1] = sq; }
    }
    __syncthreads();
    const float mean = red[0] * (1.f / C2);
    const float var  = red[1] * (1.f / C2) - mean * mean;
    const float istd = rsqrtf(var + 1e-6f);
    out[(long long)r * C2 + t]       = (x0 - mean) * istd * g[t]       + bta[t];
    out[(long long)r * C2 + t + 256] = (x1 - mean) * istd * g[t + 256] + bta[t + 256];
}

// ---------------- instance-norm stats: inv_std per (b,h) map of [C2,KV] ----------------
__global__ void inst_stats_k(const float* __restrict__ S, float* __restrict__ istd)
{
    const long long cnt  = (long long)C2 * KV;      // 917504
    const long long base = (long long)blockIdx.x * cnt;
    float s = 0.f, sq = 0.f;
    for (long long i = threadIdx.x; i < cnt; i += 1024) {
        const float v = S[base + i]; s += v; sq += v * v;
    }
    __shared__ float red[64];
#pragma unroll
    for (int o = 16; o; o >>= 1) { s += __shfl_xor_sync(~0u, s, o); sq += __shfl_xor_sync(~0u, sq, o); }
    const int w = threadIdx.x >> 5, l = threadIdx.x & 31;
    if (l == 0) { red[w] = s; red[32 + w] = sq; }
    __syncthreads();
    if (threadIdx.x < 32) {
        s = red[threadIdx.x]; sq = red[32 + threadIdx.x];
#pragma unroll
        for (int o = 16; o; o >>= 1) { s += __shfl_xor_sync(~0u, s, o); sq += __shfl_xor_sync(~0u, sq, o); }
        if (threadIdx.x == 0) {
            const float m = s / (float)cnt;
            istd[blockIdx.x] = rsqrtf(sq / (float)cnt - m * m + 1e-5f);
        }
    }
}

// softmax over kv of (x * istd)  — the per-map mean shift cancels inside softmax
__global__ void softmax_k(float* __restrict__ S, const float* __restrict__ istd)
{
    const long long row = blockIdx.x;       // [0, B*H*C2)
    const float sc = istd[row / C2];
    float* p = S + row * KV;
    const int t = threadIdx.x;
    float x[7], mx = -1e30f;
#pragma unroll
    for (int j = 0; j < 7; j++) { x[j] = p[t + j * 256] * sc; mx = fmaxf(mx, x[j]); }
    __shared__ float red[8];
#pragma unroll
    for (int o = 16; o; o >>= 1) mx = fmaxf(mx, __shfl_xor_sync(~0u, mx, o));
    const int w = t >> 5, l = t & 31;
    if (l == 0) red[w] = mx;
    __syncthreads();
    if (t < 32) {
        mx = (t < 8) ? red[t] : -1e30f;
#pragma unroll
        for (int o = 4; o; o >>= 1) mx = fmaxf(mx, __shfl_xor_sync(~0u, mx, o));
        if (t == 0) red[0] = mx;
    }
    __syncthreads();
    mx = red[0];
    __syncthreads();
    float s = 0.f;
#pragma unroll
    for (int j = 0; j < 7; j++) { x[j] = __expf(x[j] - mx); s += x[j]; }
#pragma unroll
    for (int o = 16; o; o >>= 1) s += __shfl_xor_sync(~0u, s, o);
    if (l == 0) red[w] = s;
    __syncthreads();
    if (t < 32) {
        s = (t < 8) ? red[t] : 0.f;
#pragma unroll
        for (int o = 4; o; o >>= 1) s += __shfl_xor_sync(~0u, s, o);
        if (t == 0) red[0] = s;
    }
    __syncthreads();
    const float inv = 1.f / red[0];
#pragma unroll
    for (int j = 0; j < 7; j++) p[t + j * 256] = x[j] * inv;
}

// Tsum[b,c,j] = sum_h T[b,h,c,j]
__global__ void headsum_k(const float* __restrict__ T, float* __restrict__ Ts)
{
    const long long i = (long long)blockIdx.x * 256 + threadIdx.x;   // [0, B*C2*KV)
    const long long ckv = (long long)C2 * KV;
    const long long b = i / ckv, ck = i % ckv;
    const float* p = T + b * H * ckv + ck;
    Ts[i] = p[0] + p[ckv] + p[2 * ckv] + p[3 * ckv];
}

// =================================================================
extern "C" void kernel_launch(void* const* d_in, const int* in_sizes, int n_in,
                              void* d_out, int out_size)
{
    const float* emb1   = (const float*)d_in[0];
    const float* emb2   = (const float*)d_in[1];
    const float* emb3   = (const float*)d_in[2];
    const float* Wq     = (const float*)d_in[3];
    const float* Wk     = (const float*)d_in[4];
    const float* Wv     = (const float*)d_in[5];
    const float* Wout   = (const float*)d_in[6];
    const float* ln1_g  = (const float*)d_in[7];
    const float* ln1_b  = (const float*)d_in[8];
    const float* lnall_g= (const float*)d_in[9];
    const float* lnall_b= (const float*)d_in[10];
    const float* lnffn_g= (const float*)d_in[11];
    const float* lnffn_b= (const float*)d_in[12];
    const float* fc1_w  = (const float*)d_in[13];
    const float* fc1_b  = (const float*)d_in[14];
    const float* fc2_w  = (const float*)d_in[15];
    const float* fc2_b  = (const float*)d_in[16];
    float* out = (float*)d_out;

    float *pool, *pIstd;
    cudaGetSymbolAddress((void**)&pool,  g_pool);
    cudaGetSymbolAddress((void**)&pIstd, g_istd);

    float* pE   = pool + OFF_E;
    float* pCx2 = pool + OFF_CX2;
    float* pQ   = pool + OFF_Q;
    float* pS1  = pool + OFF_S1;
    float* pS   = pool + OFF_S;
    float* pT   = pool + OFF_T;
    float* pTs  = pool + OFF_TS;
    float* pCtx = pool + OFF_CTX;
    float* pRes = pool + OFF_RES;
    float* pX2  = pool + OFF_X2;
    float* pH1  = pool + OFF_H1;

    const long long NC2 = (long long)NT * C2;        // 524288
    const long long NKV = (long long)NT * KV;        // 1835008
    const long long CKV = (long long)C2 * KV;        // 917504

    // 1. LayerNorms of inputs
    ln_concat_k<<<B * NT, 256>>>(emb1, emb2, emb3, lnall_g, lnall_b, pE);
    ln512_k<<<B * NT, 256>>>(emb2, ln1_g, ln1_b, pCx2);

    // 2. q[b,h] = cx2[b] @ Wq[h]          [1024,512]x[512,512]
    gemm_k<0,0,0><<<dim3(C2/128, NT/128, B*H), 256>>>(
        pCx2, Wq, pQ, nullptr, nullptr, NT, C2, C2,
        NC2, 0, 0, (long long)C2*C2, NC2, H, 1.f);

    // 3. S1[b,h] = q[b,h]^T @ E[b]        [512,1024]x[1024,1792]  -> R1
    gemm_k<1,0,0><<<dim3(KV/128, C2/128, B*H), 256>>>(
        pQ, pE, pS1, nullptr, nullptr, C2, KV, NT,
        (long long)H*NC2, NC2, NKV, 0, CKV, H, 1.f);

    // 4. scores = S1 @ Wk[h] / sqrt(KV)   [512,1792]x[1792,1792]  -> R2
    gemm_k<0,0,0><<<dim3(KV/128, C2/128, B*H), 256>>>(
        pS1, Wk, pS, nullptr, nullptr, C2, KV, KV,
        (long long)H*CKV, CKV, 0, (long long)KV*KV, CKV, H,
        1.f / sqrtf((float)KV));

    // 5. instance-norm stats + softmax (in place on S)
    inst_stats_k<<<B * H, 1024>>>(pS, pIstd);
    softmax_k<<<B * H * C2, 256>>>(pS, pIstd);

    // 6. T[b,h] = probs @ Wv[h]^T         [512,1792]x[1792,1792]^T -> R1
    gemm_k<0,1,0><<<dim3(KV/128, C2/128, B*H), 256>>>(
        pS, Wv, pT, nullptr, nullptr, C2, KV, KV,
        (long long)H*CKV, CKV, 0, (long long)KV*KV, CKV, H, 1.f);

    // 7. Tsum = sum over heads            -> R2
    headsum_k<<<(unsigned)(B * CKV / 256), 256>>>(pT, pTs);

    // 8. ctx[b] = E[b] @ Tsum[b]^T / H    [1024,1792]x[512,1792]^T -> R1
    gemm_k<0,1,0><<<dim3(C2/128, NT/128, B), 256>>>(
        pE, pTs, pCtx, nullptr, nullptr, NT, C2, KV,
        NKV, 0, CKV, 0, NC2, 1, 1.f / (float)H);

    // 9. res = ctx @ Wout + emb2          [8192,512]x[512,512]
    gemm_k<0,0,1><<<dim3(C2/128, (B*NT)/128, 1), 256>>>(
        pCtx, Wout, pRes, nullptr, emb2, B*NT, C2, C2,
        0, 0, 0, 0, 0, 1, 1.f);

    // 10. FFN
    ln512_k<<<B * NT, 256>>>(pRes, lnffn_g, lnffn_b, pX2);
    gemm_k<0,0,2><<<dim3(HID/128, (B*NT)/128, 1), 256>>>(
        pX2, fc1_w, pH1, fc1_b, nullptr, B*NT, HID, C2,
        0, 0, 0, 0, 0, 1, 1.f);
    gemm_k<0,0,3><<<dim3(C2/128, (B*NT)/128, 1), 256>>>(
        pH1, fc2_w, out, fc2_b, pRes, B*NT, C2, HID,
        0, 0, 0, 0, 0, 1, 1.f);
}

// round 8
// speedup vs baseline: 2.8271x; 2.8271x over previous
#include <cuda_runtime.h>
#include <math.h>
#include <stdint.h>

// Problem constants
constexpr int B   = 8;
constexpr int NT  = 1024;   // tokens
constexpr int C1  = 256;
constexpr int C2  = 512;
constexpr int C3  = 1024;
constexpr int KV  = 1792;
constexpr int H   = 4;
constexpr int HID = 2048;

// ---------------- single scratch pool with lifetime-based aliasing ----------------
//   E   [0, 14680064)                       live steps 1..8
//   R1  [14680064, 44040192)  S1(3-4) -> T(6-7) -> ctx/res/x2(8..end)
//   R2  [44040192, 73400320)  q(2-3)+cx2(1-2) -> S/probs(4-6) -> Ts(7-7.5) -> h1(fc1-fc2)
//   R3  [73400320, 90177536)  qT(2.5-3) -> WvT(5.5-6) -> TsumT(7.5-8)
constexpr long long OFF_E   = 0;
constexpr long long OFF_R1  = 14680064;
constexpr long long OFF_R2  = 44040192;
constexpr long long OFF_R3  = 73400320;
constexpr long long POOL_SZ = 90177536;               // 360.7 MB

constexpr long long OFF_S1  = OFF_R1;
constexpr long long OFF_T   = OFF_R1;
constexpr long long OFF_CTX = OFF_R1;
constexpr long long OFF_RES = OFF_R1 + 4194304;
constexpr long long OFF_X2  = OFF_R1 + 8388608;
constexpr long long OFF_Q   = OFF_R2;
constexpr long long OFF_CX2 = OFF_R2 + 17000448;
constexpr long long OFF_S   = OFF_R2;
constexpr long long OFF_TS  = OFF_R2;
constexpr long long OFF_H1  = OFF_R2;
constexpr long long OFF_QT  = OFF_R3;                 // 16,777,216 f
constexpr long long OFF_WVT = OFF_R3;                 // 12,845,056 f
constexpr long long OFF_TST = OFF_R3;                 //  7,340,032 f

__device__ __align__(128) float g_pool[POOL_SZ];
__device__ __align__(128) float g_istd[B * H];

// ---------------- helpers ----------------
__device__ __forceinline__ float to_tf32(float x) {
    uint32_t u;
    asm("cvt.rna.tf32.f32 %0, %1;" : "=r"(u) : "f"(x));
    return __uint_as_float(u);
}

__device__ __forceinline__ void mma8(float* d, const uint32_t* a, const uint32_t* b) {
    asm volatile(
        "mma.sync.aligned.m16n8k8.row.col.f32.tf32.tf32.f32 "
        "{%0,%1,%2,%3}, {%4,%5,%6,%7}, {%8,%9}, {%0,%1,%2,%3};"
        : "+f"(d[0]), "+f"(d[1]), "+f"(d[2]), "+f"(d[3])
        : "r"(a[0]), "r"(a[1]), "r"(a[2]), "r"(a[3]), "r"(b[0]), "r"(b[1]));
}

// =================================================================
// TF32 tensor-core GEMM: C[M,N] = alpha * A[M,K] @ B[K,N] (+ epilogue)
// A row-major [M,K], B row-major [K,N]. Tiles 128x128x32.
// 8 warps, each computes 64x32 via m16n8k8 mma (4x4 grid).
// EPI: 0 plain  1 +R  2 +bias,gelu  3 +bias+R
// Requires M%128==0, N%128==0, K%32==0.
// =================================================================
template <int EPI>
__global__ void __launch_bounds__(256, 2) gemm_tc(
    const float* __restrict__ A, const float* __restrict__ Bm,
    float* __restrict__ C,
    const float* __restrict__ bias, const float* __restrict__ R,
    int M, int Nn, int K,
    long long sAo, long long sAi, long long sBo, long long sBi,
    long long sC, int innerCnt, float alpha)
{
    __shared__ float As[128 * 36];   // As[m][k], stride 36 -> conflict-free
    __shared__ float Bs[32 * 136];   // Bs[k][n], stride 136 -> conflict-free

    const int z = blockIdx.z;
    A  += (long long)(z / innerCnt) * sAo + (long long)(z % innerCnt) * sAi;
    Bm += (long long)(z / innerCnt) * sBo + (long long)(z % innerCnt) * sBi;
    C  += (long long)z * sC;

    const int m0 = blockIdx.y * 128;
    const int n0 = blockIdx.x * 128;
    const int tid = threadIdx.x;
    const int lane = tid & 31;
    const int wid  = tid >> 5;
    const int warpM = (wid & 1) * 64;     // 2 warps along M
    const int warpN = (wid >> 1) * 32;    // 4 warps along N
    const int gid = lane >> 2;            // 0..7
    const int tig = lane & 3;             // 0..3

    float acc[4][4][4];
#pragma unroll
    for (int i = 0; i < 4; i++)
#pragma unroll
        for (int j = 0; j < 4; j++)
#pragma unroll
            for (int q = 0; q < 4; q++) acc[i][j][q] = 0.f;

    for (int k0 = 0; k0 < K; k0 += 32) {
        // ---- stage A tile [128m x 32k] and B tile [32k x 128n], tf32-rounded ----
#pragma unroll
        for (int j = 0; j < 4; j++) {
            const int f = tid + 256 * j;
            // A: m = f>>3, kq = (f&7)*4   (coalesced 128B per 8 lanes)
            {
                const int m = f >> 3, kq = (f & 7) * 4;
                float4 v = *reinterpret_cast<const float4*>(
                    &A[(long long)(m0 + m) * K + k0 + kq]);
                float* p = &As[m * 36 + kq];
                p[0] = to_tf32(v.x); p[1] = to_tf32(v.y);
                p[2] = to_tf32(v.z); p[3] = to_tf32(v.w);
            }
            // B: k = f>>5, nq = (f&31)*4  (coalesced 512B per warp)
            {
                const int kb = f >> 5, nq = (f & 31) * 4;
                float4 v = *reinterpret_cast<const float4*>(
                    &Bm[(long long)(k0 + kb) * Nn + n0 + nq]);
                float* p = &Bs[kb * 136 + nq];
                p[0] = to_tf32(v.x); p[1] = to_tf32(v.y);
                p[2] = to_tf32(v.z); p[3] = to_tf32(v.w);
            }
        }
        __syncthreads();

        // ---- compute: 4 k-steps of 8 ----
#pragma unroll
        for (int kk = 0; kk < 4; kk++) {
            uint32_t a[4][4], b[4][2];
#pragma unroll
            for (int i = 0; i < 4; i++) {
                const int mB = warpM + i * 16;
                const float* pa = &As[0];
                a[i][0] = __float_as_uint(pa[(mB + gid)     * 36 + kk * 8 + tig]);
                a[i][1] = __float_as_uint(pa[(mB + gid + 8) * 36 + kk * 8 + tig]);
                a[i][2] = __float_as_uint(pa[(mB + gid)     * 36 + kk * 8 + tig + 4]);
                a[i][3] = __float_as_uint(pa[(mB + gid + 8) * 36 + kk * 8 + tig + 4]);
            }
#pragma unroll
            for (int jn = 0; jn < 4; jn++) {
                const int nB = warpN + jn * 8;
                b[jn][0] = __float_as_uint(Bs[(kk * 8 + tig)     * 136 + nB + gid]);
                b[jn][1] = __float_as_uint(Bs[(kk * 8 + tig + 4) * 136 + nB + gid]);
            }
#pragma unroll
            for (int i = 0; i < 4; i++)
#pragma unroll
                for (int jn = 0; jn < 4; jn++)
                    mma8(acc[i][jn], a[i], b[jn]);
        }
        __syncthreads();
    }

    // ---- epilogue ----
#pragma unroll
    for (int i = 0; i < 4; i++) {
        const long long rA = m0 + warpM + i * 16 + gid;
        const long long rB = rA + 8;
#pragma unroll
        for (int jn = 0; jn < 4; jn++) {
            const long long cB = n0 + warpN + jn * 8 + tig * 2;
#pragma unroll
            for (int half = 0; half < 2; half++) {
                const long long r = half ? rB : rA;
                float v0 = acc[i][jn][half * 2 + 0] * alpha;
                float v1 = acc[i][jn][half * 2 + 1] * alpha;
                if (EPI == 1) { v0 += R[r * Nn + cB]; v1 += R[r * Nn + cB + 1]; }
                if (EPI == 2) {
                    v0 += bias[cB];     v0 = 0.5f * v0 * (1.f + erff(v0 * 0.70710678118654752f));
                    v1 += bias[cB + 1]; v1 = 0.5f * v1 * (1.f + erff(v1 * 0.70710678118654752f));
                }
                if (EPI == 3) {
                    v0 += bias[cB]     + R[r * Nn + cB];
                    v1 += bias[cB + 1] + R[r * Nn + cB + 1];
                }
                float2 o = make_float2(v0, v1);
                *reinterpret_cast<float2*>(&C[r * Nn + cB]) = o;
            }
        }
    }
}

// ---------------- batched transpose: in [R,C] -> out [C,R] ----------------
__global__ void transpose_k(const float* __restrict__ in, float* __restrict__ out,
                            int Rr, int Cc, long long sIn, long long sOut)
{
    __shared__ float s[32][33];
    in  += (long long)blockIdx.z * sIn;
    out += (long long)blockIdx.z * sOut;
    const int c0 = blockIdx.x * 32, r0 = blockIdx.y * 32;
    const int tx = threadIdx.x & 31, ty = threadIdx.x >> 5;   // 32 x 8
#pragma unroll
    for (int j = 0; j < 32; j += 8)
        s[ty + j][tx] = in[(long long)(r0 + ty + j) * Cc + c0 + tx];
    __syncthreads();
#pragma unroll
    for (int j = 0; j < 32; j += 8)
        out[(long long)(c0 + ty + j) * Rr + r0 + tx] = s[tx][ty + j];
}

// ---------------- LayerNorm over concatenated [256|512|1024] row ----------------
__global__ void ln_concat_k(const float* __restrict__ e1, const float* __restrict__ e2,
                            const float* __restrict__ e3, const float* __restrict__ g,
                            const float* __restrict__ bta, float* __restrict__ out)
{
    const int r = blockIdx.x;
    const int t = threadIdx.x;          // 256
    float x[7], s = 0.f, sq = 0.f;
#pragma unroll
    for (int j = 0; j < 7; j++) {
        const int i = t + j * 256;
        float v;
        if (i < C1)            v = e1[(long long)r * C1 + i];
        else if (i < C1 + C2)  v = e2[(long long)r * C2 + (i - C1)];
        else                   v = e3[(long long)r * C3 + (i - C1 - C2)];
        x[j] = v; s += v; sq += v * v;
    }
    __shared__ float red[16];
#pragma unroll
    for (int o = 16; o; o >>= 1) { s += __shfl_xor_sync(~0u, s, o); sq += __shfl_xor_sync(~0u, sq, o); }
    const int w = t >> 5, l = t & 31;
    if (l == 0) { red[w] = s; red[8 + w] = sq; }
    __syncthreads();
    if (t < 32) {
        s  = (t < 8) ? red[t]     : 0.f;
        sq = (t < 8) ? red[8 + t] : 0.f;
#pragma unroll
        for (int o = 4; o; o >>= 1) { s += __shfl_xor_sync(~0u, s, o); sq += __shfl_xor_sync(~0u, sq, o); }
        if (t == 0) { red[0] = s; red[1] = sq; }
    }
    __syncthreads();
    const float mean = red[0] * (1.f / KV);
    const float var  = red[1] * (1.f / KV) - mean * mean;
    const float istd = rsqrtf(var + 1e-6f);
#pragma unroll
    for (int j = 0; j < 7; j++) {
        const int i = t + j * 256;
        out[(long long)r * KV + i] = (x[j] - mean) * istd * g[i] + bta[i];
    }
}

// ---------------- LayerNorm over 512-wide row ----------------
__global__ void ln512_k(const float* __restrict__ in, const float* __restrict__ g,
                        const float* __restrict__ bta, float* __restrict__ out)
{
    const int r = blockIdx.x;
    const int t = threadIdx.x;          // 256
    float x0 = in[(long long)r * C2 + t];
    float x1 = in[(long long)r * C2 + t + 256];
    float s = x0 + x1, sq = x0 * x0 + x1 * x1;
    __shared__ float red[16];
#pragma unroll
    for (int o = 16; o; o >>= 1) { s += __shfl_xor_sync(~0u, s, o); sq += __shfl_xor_sync(~0u, sq, o); }
    const int w = t >> 5, l = t & 31;
    if (l == 0) { red[w] = s; red[8 + w] = sq; }
    __syncthreads();
    if (t < 32) {
        s  = (t < 8) ? red[t]     : 0.f;
        sq = (t < 8) ? red[8 + t] : 0.f;
#pragma unroll
        for (int o = 4; o; o >>= 1) { s += __shfl_xor_sync(~0u, s, o); sq += __shfl_xor_sync(~0u, sq, o); }
        if (t == 0) { red[0] = s; red[1] = sq; }
    }
    __syncthreads();
    const float mean = red[0] * (1.f / C2);
    const float var  = red[1] * (1.f / C2) - mean * mean;
    const float istd = rsqrtf(var + 1e-6f);
    out[(long long)r * C2 + t]       = (x0 - mean) * istd * g[t]       + bta[t];
    out[(long long)r * C2 + t + 256] = (x1 - mean) * istd * g[t + 256] + bta[t + 256];
}

// ---------------- instance-norm stats: inv_std per (b,h) map of [C2,KV] ----------------
__global__ void inst_stats_k(const float* __restrict__ S, float* __restrict__ istd)
{
    const long long cnt  = (long long)C2 * KV;
    const long long base = (long long)blockIdx.x * cnt;
    float s = 0.f, sq = 0.f;
    for (long long i = threadIdx.x; i < cnt; i += 1024) {
        const float v = S[base + i]; s += v; sq += v * v;
    }
    __shared__ float red[64];
#pragma unroll
    for (int o = 16; o; o >>= 1) { s += __shfl_xor_sync(~0u, s, o); sq += __shfl_xor_sync(~0u, sq, o); }
    const int w = threadIdx.x >> 5, l = threadIdx.x & 31;
    if (l == 0) { red[w] = s; red[32 + w] = sq; }
    __syncthreads();
    if (threadIdx.x < 32) {
        s = red[threadIdx.x]; sq = red[32 + threadIdx.x];
#pragma unroll
        for (int o = 16; o; o >>= 1) { s += __shfl_xor_sync(~0u, s, o); sq += __shfl_xor_sync(~0u, sq, o); }
        if (threadIdx.x == 0) {
            const float m = s / (float)cnt;
            istd[blockIdx.x] = rsqrtf(sq / (float)cnt - m * m + 1e-5f);
        }
    }
}

// softmax over kv of (x * istd) — the per-map mean shift cancels inside softmax
__global__ void softmax_k(float* __restrict__ S, const float* __restrict__ istd)
{
    const long long row = blockIdx.x;       // [0, B*H*C2)
    const float sc = istd[row / C2];
    float* p = S + row * KV;
    const int t = threadIdx.x;
    float x[7], mx = -1e30f;
#pragma unroll
    for (int j = 0; j < 7; j++) { x[j] = p[t + j * 256] * sc; mx = fmaxf(mx, x[j]); }
    __shared__ float red[8];
#pragma unroll
    for (int o = 16; o; o >>= 1) mx = fmaxf(mx, __shfl_xor_sync(~0u, mx, o));
    const int w = t >> 5, l = t & 31;
    if (l == 0) red[w] = mx;
    __syncthreads();
    if (t < 32) {
        mx = (t < 8) ? red[t] : -1e30f;
#pragma unroll
        for (int o = 4; o; o >>= 1) mx = fmaxf(mx, __shfl_xor_sync(~0u, mx, o));
        if (t == 0) red[0] = mx;
    }
    __syncthreads();
    mx = red[0];
    __syncthreads();
    float s = 0.f;
#pragma unroll
    for (int j = 0; j < 7; j++) { x[j] = __expf(x[j] - mx); s += x[j]; }
#pragma unroll
    for (int o = 16; o; o >>= 1) s += __shfl_xor_sync(~0u, s, o);
    if (l == 0) red[w] = s;
    __syncthreads();
    if (t < 32) {
        s = (t < 8) ? red[t] : 0.f;
#pragma unroll
        for (int o = 4; o; o >>= 1) s += __shfl_xor_sync(~0u, s, o);
        if (t == 0) red[0] = s;
    }
    __syncthreads();
    const float inv = 1.f / red[0];
#pragma unroll
    for (int j = 0; j < 7; j++) p[t + j * 256] = x[j] * inv;
}

// Tsum[b,c,j] = sum_h T[b,h,c,j]
__global__ void headsum_k(const float* __restrict__ T, float* __restrict__ Ts)
{
    const long long i = (long long)blockIdx.x * 256 + threadIdx.x;
    const long long ckv = (long long)C2 * KV;
    const long long b = i / ckv, ck = i % ckv;
    const float* p = T + b * H * ckv + ck;
    Ts[i] = p[0] + p[ckv] + p[2 * ckv] + p[3 * ckv];
}

// =================================================================
extern "C" void kernel_launch(void* const* d_in, const int* in_sizes, int n_in,
                              void* d_out, int out_size)
{
    const float* emb1   = (const float*)d_in[0];
    const float* emb2   = (const float*)d_in[1];
    const float* emb3   = (const float*)d_in[2];
    const float* Wq     = (const float*)d_in[3];
    const float* Wk     = (const float*)d_in[4];
    const float* Wv     = (const float*)d_in[5];
    const float* Wout   = (const float*)d_in[6];
    const float* ln1_g  = (const float*)d_in[7];
    const float* ln1_b  = (const float*)d_in[8];
    const float* lnall_g= (const float*)d_in[9];
    const float* lnall_b= (const float*)d_in[10];
    const float* lnffn_g= (const float*)d_in[11];
    const float* lnffn_b= (const float*)d_in[12];
    const float* fc1_w  = (const float*)d_in[13];
    const float* fc1_b  = (const float*)d_in[14];
    const float* fc2_w  = (const float*)d_in[15];
    const float* fc2_b  = (const float*)d_in[16];
    float* out = (float*)d_out;

    float *pool, *pIstd;
    cudaGetSymbolAddress((void**)&pool,  g_pool);
    cudaGetSymbolAddress((void**)&pIstd, g_istd);

    float* pE   = pool + OFF_E;
    float* pCx2 = pool + OFF_CX2;
    float* pQ   = pool + OFF_Q;
    float* pQT  = pool + OFF_QT;
    float* pS1  = pool + OFF_S1;
    float* pS   = pool + OFF_S;
    float* pWvT = pool + OFF_WVT;
    float* pT   = pool + OFF_T;
    float* pTs  = pool + OFF_TS;
    float* pTsT = pool + OFF_TST;
    float* pCtx = pool + OFF_CTX;
    float* pRes = pool + OFF_RES;
    float* pX2  = pool + OFF_X2;
    float* pH1  = pool + OFF_H1;

    const long long NC2 = (long long)NT * C2;        // 524288
    const long long NKV = (long long)NT * KV;        // 1835008
    const long long CKV = (long long)C2 * KV;        // 917504
    const long long KVKV = (long long)KV * KV;       // 3211264

    // 1. LayerNorms of inputs
    ln_concat_k<<<B * NT, 256>>>(emb1, emb2, emb3, lnall_g, lnall_b, pE);
    ln512_k<<<B * NT, 256>>>(emb2, ln1_g, ln1_b, pCx2);

    // 2. q[b,h] = cx2[b] @ Wq[h]          [1024,512]x[512,512]
    gemm_tc<0><<<dim3(C2/128, NT/128, B*H), 256>>>(
        pCx2, Wq, pQ, nullptr, nullptr, NT, C2, C2,
        NC2, 0, 0, (long long)C2*C2, NC2, H, 1.f);

    // 2.5 transpose q -> qT [C2,NT] per (b,h)
    transpose_k<<<dim3(C2/32, NT/32, B*H), 256>>>(pQ, pQT, NT, C2, NC2, NC2);

    // 3. S1[b,h] = qT[b,h] @ E[b]         [512,1024]x[1024,1792]  -> R1
    gemm_tc<0><<<dim3(KV/128, C2/128, B*H), 256>>>(
        pQT, pE, pS1, nullptr, nullptr, C2, KV, NT,
        (long long)H*NC2, NC2, NKV, 0, CKV, H, 1.f);

    // 4. scores = S1 @ Wk[h] / sqrt(KV)   [512,1792]x[1792,1792]  -> R2
    gemm_tc<0><<<dim3(KV/128, C2/128, B*H), 256>>>(
        pS1, Wk, pS, nullptr, nullptr, C2, KV, KV,
        (long long)H*CKV, CKV, 0, KVKV, CKV, H,
        1.f / sqrtf((float)KV));

    // 5. instance-norm stats + softmax (in place on S)
    inst_stats_k<<<B * H, 1024>>>(pS, pIstd);
    softmax_k<<<B * H * C2, 256>>>(pS, pIstd);

    // 5.5 transpose Wv -> WvT [KV,KV] per head
    transpose_k<<<dim3(KV/32, KV/32, H), 256>>>(Wv, pWvT, KV, KV, KVKV, KVKV);

    // 6. T[b,h] = probs @ WvT[h]          [512,1792]x[1792,1792]  -> R1
    gemm_tc<0><<<dim3(KV/128, C2/128, B*H), 256>>>(
        pS, pWvT, pT, nullptr, nullptr, C2, KV, KV,
        (long long)H*CKV, CKV, 0, KVKV, CKV, H, 1.f);

    // 7. Tsum = sum over heads            -> R2
    headsum_k<<<(unsigned)(B * CKV / 256), 256>>>(pT, pTs);

    // 7.5 transpose Tsum [C2,KV] -> TsumT [KV,C2] per b
    transpose_k<<<dim3(KV/32, C2/32, B), 256>>>(pTs, pTsT, C2, KV, CKV, CKV);

    // 8. ctx[b] = E[b] @ TsumT[b] / H     [1024,1792]x[1792,512]  -> R1
    gemm_tc<0><<<dim3(C2/128, NT/128, B), 256>>>(
        pE, pTsT, pCtx, nullptr, nullptr, NT, C2, KV,
        NKV, 0, CKV, 0, NC2, 1, 1.f / (float)H);

    // 9. res = ctx @ Wout + emb2          [8192,512]x[512,512]
    gemm_tc<1><<<dim3(C2/128, (B*NT)/128, 1), 256>>>(
        pCtx, Wout, pRes, nullptr, emb2, B*NT, C2, C2,
        0, 0, 0, 0, 0, 1, 1.f);

    // 10. FFN
    ln512_k<<<B * NT, 256>>>(pRes, lnffn_g, lnffn_b, pX2);
    gemm_tc<2><<<dim3(HID/128, (B*NT)/128, 1), 256>>>(
        pX2, fc1_w, pH1, fc1_b, nullptr, B*NT, HID, C2,
        0, 0, 0, 0, 0, 1, 1.f);
    gemm_tc<3><<<dim3(C2/128, (B*NT)/128, 1), 256>>>(
        pH1, fc2_w, out, fc2_b, pRes, B*NT, C2, HID,
        0, 0, 0, 0, 0, 1, 1.f);
}